// round 13
// baseline (speedup 1.0000x reference)
#include <cuda_runtime.h>
#include <math.h>

typedef unsigned long long ull;

// LureSystem on GB300 — R12. R10 structure (split cluster arrive/wait, xe
// K-split across the w-exchange window) rebuilt with:
//  * 1024 threads (32 warps, occ 50%) for latency hiding
//  * K-paired fma.rn.f32x2: both operands natural 64-bit vectors -> zero
//    packing; weights row-major with per-row 4-float rotation, conflict-free.
// 16 groups x 8-CTA clusters.

#define NSTEPS 2048
#define RANKS 8
#define GROUPS 16
#define BT 16
#define THREADS 1024

#define S_ACT 580           // [x(256)|d(64)|w(256)]; 580%32==4 -> act loads CF
#define SW1 352             // w-weight row stride (352%32==0)
#define SW2 608             // xe-weight row stride (608%32==0)
#define PS 40               // partials batch stride (40%32==8 -> stores CF)
#define PAR 640             // per-chunk partials stride = 16*40

// SMEM float offsets
#define OFF_W1 0            // [32][352] rows rw..rw+31 of [C2|D21], rotated
#define OFF_W2 11264        // [40][608] rows 0-31 [A|B|B2], 32-39 fused E, rotated
#define OFF_ACT 35584       // [16][580]
#define OFF_PAR 44864       // 16*640 = 10240
#define SMEM_FLOATS 55104   // 220416 bytes

#define E_SIZE (256 * NSTEPS * 64)
#define BASE_X E_SIZE
#define BASE_W (E_SIZE + 256 * 256)

__device__ float g_EW[64 * 576];
__device__ float g_wbuf[GROUPS * BT * 256];
__device__ float g_xbuf[GROUPS * BT * 256];

__device__ __forceinline__ void cluster_arrive() {
    asm volatile("barrier.cluster.arrive.aligned;" ::: "memory");
}
__device__ __forceinline__ void cluster_wait() {
    asm volatile("barrier.cluster.wait.aligned;" ::: "memory");
}
__device__ __forceinline__ void fma2(ull& acc, ull m, ull a) {
    asm("fma.rn.f32x2 %0, %1, %2, %0;" : "+l"(acc) : "l"(m), "l"(a));
}
__device__ __forceinline__ float foldp(ull p) {
    float lo, hi;
    asm("mov.b64 {%0, %1}, %2;" : "=f"(lo), "=f"(hi) : "l"(p));
    return lo + hi;
}

// w-phase micro-tile: 4 rows (stride 8) x 2 batches (stride 8) over K=20.
__device__ __forceinline__ void mm_w(const float* __restrict__ Wp,
                                     const float* __restrict__ Ap,
                                     ull (&acc)[4][2]) {
#pragma unroll
    for (int j4 = 0; j4 < 5; j4++) {
        ulonglong2 w[4], a[2];
#pragma unroll
        for (int i = 0; i < 4; i++)
            w[i] = *reinterpret_cast<const ulonglong2*>(Wp + i * (8 * SW1) + 4 * j4);
#pragma unroll
        for (int kk = 0; kk < 2; kk++)
            a[kk] = *reinterpret_cast<const ulonglong2*>(Ap + kk * (8 * S_ACT) + 4 * j4);
#pragma unroll
        for (int i = 0; i < 4; i++)
#pragma unroll
            for (int kk = 0; kk < 2; kk++) fma2(acc[i][kk], w[i].x, a[kk].x);
#pragma unroll
        for (int i = 0; i < 4; i++)
#pragma unroll
            for (int kk = 0; kk < 2; kk++) fma2(acc[i][kk], w[i].y, a[kk].y);
    }
}

// xe-phase micro-tile: 5 rows (stride 8) x 2 batches (stride 8) over K=4*L4.
template <int L4>
__device__ __forceinline__ void mm_xe(const float* __restrict__ Wp,
                                      const float* __restrict__ Ap,
                                      ull (&acc)[5][2]) {
#pragma unroll
    for (int j4 = 0; j4 < L4; j4++) {
        ulonglong2 w[5], a[2];
#pragma unroll
        for (int i = 0; i < 5; i++)
            w[i] = *reinterpret_cast<const ulonglong2*>(Wp + i * (8 * SW2) + 4 * j4);
#pragma unroll
        for (int kk = 0; kk < 2; kk++)
            a[kk] = *reinterpret_cast<const ulonglong2*>(Ap + kk * (8 * S_ACT) + 4 * j4);
#pragma unroll
        for (int i = 0; i < 5; i++)
#pragma unroll
            for (int kk = 0; kk < 2; kk++) fma2(acc[i][kk], w[i].x, a[kk].x);
#pragma unroll
        for (int i = 0; i < 5; i++)
#pragma unroll
            for (int kk = 0; kk < 2; kk++) fma2(acc[i][kk], w[i].y, a[kk].y);
    }
}

// ---- pre-kernel: fused e-weights EW = [C@A | C@B + D | C@B2 + D12] ----
__global__ void fuse_kernel(const float* __restrict__ A, const float* __restrict__ B,
                            const float* __restrict__ B2, const float* __restrict__ C,
                            const float* __restrict__ D, const float* __restrict__ D12) {
    __shared__ float c[256];
    int i = blockIdx.x;
    for (int idx = threadIdx.x; idx < 256; idx += blockDim.x) c[idx] = C[i * 256 + idx];
    __syncthreads();
    for (int j = threadIdx.x; j < 576; j += blockDim.x) {
        float s = 0.f;
        if (j < 256) {
            for (int kk = 0; kk < 256; kk++) s = fmaf(c[kk], A[kk * 256 + j], s);
        } else if (j < 320) {
            int jj = j - 256;
            for (int kk = 0; kk < 256; kk++) s = fmaf(c[kk], B[kk * 64 + jj], s);
            s += D[i * 64 + jj];
        } else {
            int jj = j - 320;
            for (int kk = 0; kk < 256; kk++) s = fmaf(c[kk], B2[kk * 256 + jj], s);
            s += D12[i * 256 + jj];
        }
        g_EW[i * 576 + j] = s;
    }
}

__global__ void __cluster_dims__(RANKS, 1, 1) __launch_bounds__(THREADS, 1)
lure_kernel(const float* __restrict__ dseq,
            const float* __restrict__ x0,
            const float* __restrict__ Amat,
            const float* __restrict__ Bmat,
            const float* __restrict__ B2mat,
            const float* __restrict__ C2mat,
            const float* __restrict__ D21mat,
            float* __restrict__ out) {
    extern __shared__ float smem[];
    float* sW1  = smem + OFF_W1;
    float* sW2  = smem + OFF_W2;
    float* sAct = smem + OFF_ACT;
    float* sPar = smem + OFF_PAR;

    const int t = threadIdx.x;
    const int g = blockIdx.x >> 3;
    const int r = blockIdx.x & 7;
    const int rw = r * 32;
    const int re = r * 8;

    // ---- resident weights, row-major with per-row rotation 4*(row&7) ----
    for (int idx = t; idx < 32 * 320; idx += THREADS) {
        int row = idx / 320, j = idx % 320;
        float v = (j < 256) ? C2mat[(rw + row) * 256 + j]
                            : D21mat[(rw + row) * 64 + (j - 256)];
        sW1[row * SW1 + j + 4 * (row & 7)] = v;
    }
    for (int idx = t; idx < 40 * 576; idx += THREADS) {
        int row = idx / 576, j = idx % 576;
        float v;
        if (row < 32) {
            int gr = rw + row;
            if (j < 256)      v = Amat[gr * 256 + j];
            else if (j < 320) v = Bmat[gr * 64 + (j - 256)];
            else              v = B2mat[gr * 256 + (j - 320)];
        } else {
            v = g_EW[(re + row - 32) * 576 + j];
        }
        sW2[row * SW2 + j + 4 * (row & 7)] = v;
    }
    for (int idx = t; idx < BT * 256; idx += THREADS) {
        int b = idx >> 8, col = idx & 255;
        sAct[b * S_ACT + col] = x0[(g * BT + b) * 256 + col];
    }
    if (t < BT * 64) {
        int b = t >> 6, j = t & 63;
        sAct[b * S_ACT + 256 + j] = dseq[(size_t)(g * BT + b) * (NSTEPS * 64) + j];
    }

    // ---- decomposition: chunk = t>>6 (16), tile = t&63 ----
    const int chunk = t >> 6, tile = t & 63;
    const int q = tile & 7;            // row lane (rows q+8i)
    const int b0 = tile >> 3;          // batch lane (b = b0, b0+8)
    const int j0w = chunk * 20;
    const int j0A = chunk * 20;        // xe part A over [0,320)
    const int j0B = 320 + chunk * 16;  // xe part B over [320,576)

    const float* Wp_w = sW1 + q * SW1 + 4 * q;       // rot = 4*(q&7) = 4q
    const float* Wp_x = sW2 + q * SW2 + 4 * q;       // rows q+8i, same rot
    const float* Ap   = sAct + b0 * S_ACT;
    float* Pw = sPar + chunk * PAR + b0 * PS + q;

    const int rb = t >> 5, rr = t & 31;              // w reduce (t<512)
    const int xb = t / 40, xr = t % 40;              // xe reduce (t<640)

    float* gw = g_wbuf + g * (BT * 256);
    float* gx = g_xbuf + g * (BT * 256);
    const float4* gw4 = reinterpret_cast<const float4*>(gw);
    const float4* gx4 = reinterpret_cast<const float4*>(gx);

    float dpre = 0.f;
    const int db = t >> 6, dj = t & 63;              // one d elem per thread

    __syncthreads();

    for (int k = 0; k < NSTEPS; ++k) {
        // ---- w-phase: 32 rows, K=320, 16 chunks x K20 ----
        {
            ull acc[4][2] = {{0, 0}, {0, 0}, {0, 0}, {0, 0}};
            mm_w(Wp_w + j0w, Ap + j0w, acc);
#pragma unroll
            for (int i = 0; i < 4; i++)
#pragma unroll
                for (int kk = 0; kk < 2; kk++)
                    Pw[kk * (8 * PS) + i * 8] = foldp(acc[i][kk]);
        }
        __syncthreads();
        if (t < 512) {
            float s = 0.f;
#pragma unroll
            for (int c = 0; c < 16; c++) s += sPar[c * PAR + rb * PS + rr];
            __stcg(&gw[rb * 256 + rw + rr], tanhf(s));
        }
        cluster_arrive();   // release w; overlap window below

        // ---- overlap: xe part A (x|d region) + d_{k+1} prefetch ----
        ull xacc[5][2] = {{0, 0}, {0, 0}, {0, 0}, {0, 0}, {0, 0}};
        mm_xe<5>(Wp_x + j0A, Ap + j0A, xacc);
        {
            int kp = (k + 1 < NSTEPS) ? (k + 1) : (NSTEPS - 1);
            dpre = dseq[(size_t)(g * BT + db) * (NSTEPS * 64) + (size_t)kp * 64 + dj];
        }
        cluster_wait();
        // gather full w: 1024 float4, one per thread
        {
            float4 v = __ldcg(gw4 + t);
            *reinterpret_cast<float4*>(&sAct[(t >> 6) * S_ACT + 320 + (t & 63) * 4]) = v;
        }
        __syncthreads();

        // ---- xe part B (w region), fold, reduce ----
        mm_xe<4>(Wp_x + j0B, Ap + j0B, xacc);
        {
            float* Px = sPar + chunk * PAR + b0 * PS + q;
#pragma unroll
            for (int i = 0; i < 5; i++)
#pragma unroll
                for (int kk = 0; kk < 2; kk++)
                    Px[kk * (8 * PS) + i * 8] = foldp(xacc[i][kk]);
        }
        __syncthreads();
        float xres = 0.f;
        if (t < 640) {
#pragma unroll
            for (int c = 0; c < 16; c++) xres += sPar[c * PAR + t];
            if (xr < 32) __stcg(&gx[xb * 256 + rw + xr], xres);
        }
        cluster_arrive();   // release x; overlap e-store + d-commit

        if (t < 640 && xr >= 32)
            out[(size_t)(g * BT + xb) * (NSTEPS * 64) + (size_t)k * 64 + re + (xr - 32)] = xres;
        sAct[db * S_ACT + 256 + dj] = dpre;

        cluster_wait();
        // gather full x_new: 1024 float4
        {
            float4 v = __ldcg(gx4 + t);
            *reinterpret_cast<float4*>(&sAct[(t >> 6) * S_ACT + (t & 63) * 4]) = v;
        }
        __syncthreads();
    }

    // final states: x_final (act x-part), w_{N-1} (act w-part)
    if (t < 512) {
        int b = t >> 5, row = t & 31;
        size_t gb = (size_t)(g * BT + b);
        out[BASE_X + gb * 256 + rw + row] = sAct[b * S_ACT + rw + row];
        out[BASE_W + gb * 256 + rw + row] = sAct[b * S_ACT + 320 + rw + row];
    }
}

extern "C" void kernel_launch(void* const* d_in, const int* in_sizes, int n_in,
                              void* d_out, int out_size) {
    (void)in_sizes; (void)n_in; (void)out_size;
    const float* dseq = (const float*)d_in[0];
    const float* x0   = (const float*)d_in[1];
    const float* A    = (const float*)d_in[2];
    const float* B    = (const float*)d_in[3];
    const float* B2   = (const float*)d_in[4];
    const float* C    = (const float*)d_in[5];
    const float* D    = (const float*)d_in[6];
    const float* D12  = (const float*)d_in[7];
    const float* C2   = (const float*)d_in[8];
    const float* D21  = (const float*)d_in[9];
    float* out = (float*)d_out;

    fuse_kernel<<<64, 256>>>(A, B, B2, C, D, D12);

    const size_t smem_bytes = (size_t)SMEM_FLOATS * sizeof(float);
    cudaFuncSetAttribute(lure_kernel, cudaFuncAttributeMaxDynamicSharedMemorySize,
                         (int)smem_bytes);
    lure_kernel<<<GROUPS * RANKS, THREADS, smem_bytes>>>(dseq, x0, A, B, B2,
                                                         C2, D21, out);
}

// round 15
// speedup vs baseline: 1.1306x; 1.1306x over previous
#include <cuda_runtime.h>
#include <math.h>

typedef unsigned long long ull;
typedef unsigned int uint32;

// LureSystem on GB300 — R13. R10 skeleton (640 thr, proven 26.5ms) with the
// L2-scratch exchanges replaced by DSMEM direct stores (mapa +
// st.shared::cluster), ordered by barrier.cluster release/acquire. xe part-A
// hoisted before the w-phase so all x-readers precede the w-arrive (makes the
// direct x-store race-free). No gathers, no L2 scratch, 3 syncthreads/step.

#define NSTEPS 2048
#define RANKS 8
#define GROUPS 16
#define BT 16
#define THREADS 640

#define S_ACT 584           // [x(256)|d(64)|w(256)]; %32==8
#define PS_W 40             // w partials batch stride
#define PARW 640            // w per-chunk stride = 16*40
#define PS_X 44             // xe partials batch stride
#define PARX 712            // xe per-chunk stride = 16*44 + 8 (bank stagger)

// SMEM float offsets
#define OFF_W1T 0           // [320][32]  [C2|D21]^T rows rw..rw+31
#define OFF_W2T 10240       // [576][40]  rows 0-31 [A|B|B2]^T, 32-39 fused E^T
#define OFF_ACT 33280       // [16][584]
#define OFF_PAR 42624       // max(20*640, 16*712) = 12800
#define SMEM_FLOATS 55424   // 221696 bytes

#define E_SIZE (256 * NSTEPS * 64)
#define BASE_X E_SIZE
#define BASE_W (E_SIZE + 256 * 256)

__device__ float g_EW[64 * 576];

__device__ __forceinline__ void cluster_arrive() {
    asm volatile("barrier.cluster.arrive.aligned;" ::: "memory");
}
__device__ __forceinline__ void cluster_wait() {
    asm volatile("barrier.cluster.wait.aligned;" ::: "memory");
}
__device__ __forceinline__ uint32 smem_u32(const void* p) {
    uint32 a;
    asm("{ .reg .u64 tmp; cvta.to.shared.u64 tmp, %1; cvt.u32.u64 %0, tmp; }"
        : "=r"(a) : "l"(p));
    return a;
}
__device__ __forceinline__ uint32 mapa_rank(uint32 addr, uint32 rank) {
    uint32 r;
    asm("mapa.shared::cluster.u32 %0, %1, %2;" : "=r"(r) : "r"(addr), "r"(rank));
    return r;
}
__device__ __forceinline__ void st_cluster(uint32 addr, float v) {
    asm volatile("st.shared::cluster.b32 [%0], %1;"
                 :: "r"(addr), "r"(__float_as_uint(v)) : "memory");
}

__device__ __forceinline__ void fma2(ull& acc, ull m, ull a) {
    asm("fma.rn.f32x2 %0, %1, %2, %0;" : "+l"(acc) : "l"(m), "l"(a));
}
__device__ __forceinline__ ull pack2(float x) {
    ull r; asm("mov.b64 %0, {%1, %1};" : "=l"(r) : "f"(x)); return r;
}

// 4 rows x 4 batches (b = b0 + 4*kk) over K-chunk of 4*L4 with weight
// double-buffering. Accumulators persist across calls (passed by reference).
template <int L4, int WS>
__device__ __forceinline__ void mmT(const float* __restrict__ WT,
                                    const float* __restrict__ Act,
                                    ull (&a01)[4], ull (&a23)[4]) {
    ulonglong2 wv[2][4];
#pragma unroll
    for (int jj = 0; jj < 4; jj++)
        wv[0][jj] = *reinterpret_cast<const ulonglong2*>(WT + jj * WS);
#pragma unroll
    for (int j4 = 0; j4 < L4; j4++) {
        const int cur = j4 & 1, nxt = cur ^ 1;
        if (j4 + 1 < L4) {
#pragma unroll
            for (int jj = 0; jj < 4; jj++)
                wv[nxt][jj] = *reinterpret_cast<const ulonglong2*>(
                    WT + (4 * (j4 + 1) + jj) * WS);
        }
        float av[4][4];
#pragma unroll
        for (int kk = 0; kk < 4; kk++) {
            float4 t4 = *reinterpret_cast<const float4*>(Act + kk * (4 * S_ACT) + 4 * j4);
            av[kk][0] = t4.x; av[kk][1] = t4.y; av[kk][2] = t4.z; av[kk][3] = t4.w;
        }
#pragma unroll
        for (int jj = 0; jj < 4; jj++) {
#pragma unroll
            for (int kk = 0; kk < 4; kk++) {
                ull aa = pack2(av[kk][jj]);
                fma2(a01[kk], wv[cur][jj].x, aa);
                fma2(a23[kk], wv[cur][jj].y, aa);
            }
        }
    }
}

// ---- pre-kernel: fused e-weights EW = [C@A | C@B + D | C@B2 + D12] ----
__global__ void fuse_kernel(const float* __restrict__ A, const float* __restrict__ B,
                            const float* __restrict__ B2, const float* __restrict__ C,
                            const float* __restrict__ D, const float* __restrict__ D12) {
    __shared__ float c[256];
    int i = blockIdx.x;
    for (int idx = threadIdx.x; idx < 256; idx += blockDim.x) c[idx] = C[i * 256 + idx];
    __syncthreads();
    for (int j = threadIdx.x; j < 576; j += blockDim.x) {
        float s = 0.f;
        if (j < 256) {
            for (int kk = 0; kk < 256; kk++) s = fmaf(c[kk], A[kk * 256 + j], s);
        } else if (j < 320) {
            int jj = j - 256;
            for (int kk = 0; kk < 256; kk++) s = fmaf(c[kk], B[kk * 64 + jj], s);
            s += D[i * 64 + jj];
        } else {
            int jj = j - 320;
            for (int kk = 0; kk < 256; kk++) s = fmaf(c[kk], B2[kk * 256 + jj], s);
            s += D12[i * 256 + jj];
        }
        g_EW[i * 576 + j] = s;
    }
}

__global__ void __cluster_dims__(RANKS, 1, 1) __launch_bounds__(THREADS, 1)
lure_kernel(const float* __restrict__ dseq,
            const float* __restrict__ x0,
            const float* __restrict__ Amat,
            const float* __restrict__ Bmat,
            const float* __restrict__ B2mat,
            const float* __restrict__ C2mat,
            const float* __restrict__ D21mat,
            float* __restrict__ out) {
    extern __shared__ float smem[];
    float* sW1T = smem + OFF_W1T;
    float* sW2T = smem + OFF_W2T;
    float* sAct = smem + OFF_ACT;
    float* sPar = smem + OFF_PAR;

    const int t = threadIdx.x;
    const int g = blockIdx.x >> 3;
    const int r = blockIdx.x & 7;
    const int rw = r * 32;
    const int re = r * 8;

    // ---- resident weights (transposed [K][row]) ----
    for (int idx = t; idx < 320 * 32; idx += THREADS) {
        int row = idx & 31, j = idx >> 5;
        float v = (j < 256) ? C2mat[(rw + row) * 256 + j]
                            : D21mat[(rw + row) * 64 + (j - 256)];
        sW1T[j * 32 + row] = v;
    }
    for (int idx = t; idx < 576 * 40; idx += THREADS) {
        int row = idx % 40, j = idx / 40;
        float v;
        if (row < 32) {
            int gr = rw + row;
            if (j < 256)      v = Amat[gr * 256 + j];
            else if (j < 320) v = Bmat[gr * 64 + (j - 256)];
            else              v = B2mat[gr * 256 + (j - 320)];
        } else {
            v = g_EW[(re + row - 32) * 576 + j];
        }
        sW2T[j * 40 + row] = v;
    }
    for (int idx = t; idx < BT * 256; idx += THREADS) {
        int b = idx >> 8, col = idx & 255;
        sAct[b * S_ACT + col] = x0[(g * BT + b) * 256 + col];
    }
    for (int idx = t; idx < BT * 64; idx += THREADS) {
        int b = idx >> 6, j = idx & 63;
        sAct[b * S_ACT + 256 + j] = dseq[(size_t)(g * BT + b) * (NSTEPS * 64) + j];
    }

    // ---- work decomposition (identical to R10) ----
    const int lane = t & 31, warp = t >> 5;
    const int row0w = (lane & 7) * 4, b0w = lane >> 3;
    const int j0w = warp * 16;
    const int tl = t % 40, cx = t / 40;
    const int b0x = tl / 10, row0x = (tl % 10) * 4;
    const int j0A = cx * 20;
    const int j0B = 320 + cx * 16;
    const int rb = t >> 5, rr = t & 31;          // w reduce (t<512)
    const int xb = t / 40, xr = t % 40;          // xe reduce (all 640)

    // DSMEM peer bases for sAct
    const uint32 actu = smem_u32(sAct);
    uint32 peer[RANKS];
#pragma unroll
    for (int p = 0; p < RANKS; p++) peer[p] = mapa_rank(actu, p);
    const uint32 offw = (uint32)(rb * S_ACT + 320 + rw + rr) * 4;   // w dest
    const uint32 offx = (uint32)(xb * S_ACT + rw + xr) * 4;         // x dest

    float dpre0 = 0.f, dpre1 = 0.f;
    const int d0b = t >> 6, d0j = t & 63;        // idx t (<640)
    const int i1 = t + THREADS;                  // idx t+640 (<1024 -> t<384)
    const int d1b = i1 >> 6, d1j = i1 & 63;

    __syncthreads();
    cluster_arrive();    // init complete before any DSMEM traffic
    cluster_wait();

    for (int k = 0; k < NSTEPS; ++k) {
        // ---- xe part-A (x|d region) FIRST: all x-readers precede w-arrive ----
        ull x01[4] = {0, 0, 0, 0}, x23[4] = {0, 0, 0, 0};
        mmT<5, 40>(sW2T + j0A * 40 + row0x, sAct + b0x * S_ACT + j0A, x01, x23);

        // ---- w-phase mm: 32 rows, K=320 ----
        {
            ull a01[4] = {0, 0, 0, 0}, a23[4] = {0, 0, 0, 0};
            mmT<4, 32>(sW1T + j0w * 32 + row0w, sAct + b0w * S_ACT + j0w, a01, a23);
            float* P = sPar + warp * PARW + b0w * PS_W + row0w;
#pragma unroll
            for (int kk = 0; kk < 4; kk++)
                *reinterpret_cast<ulonglong2*>(P + kk * (4 * PS_W)) =
                    make_ulonglong2(a01[kk], a23[kk]);
        }
        __syncthreads();
        if (t < 512) {
            float s = 0.f;
#pragma unroll
            for (int c = 0; c < 16; c++) s += sPar[c * PARW + rb * PS_W + rr];
            // chunks 16..19
#pragma unroll
            for (int c = 16; c < 20; c++) s += sPar[c * PARW + rb * PS_W + rr];
            float v = tanhf(s);
            // direct-store w value into all 8 ranks' sAct
#pragma unroll
            for (int p = 0; p < RANKS; p++) st_cluster(peer[p] + offw, v);
        }
        cluster_arrive();   // release w stores

        // window: d_{k+1} prefetch
        {
            int kp = (k + 1 < NSTEPS) ? (k + 1) : (NSTEPS - 1);
            dpre0 = dseq[(size_t)(g * BT + d0b) * (NSTEPS * 64) + (size_t)kp * 64 + d0j];
            if (i1 < 1024)
                dpre1 = dseq[(size_t)(g * BT + d1b) * (NSTEPS * 64) + (size_t)kp * 64 + d1j];
        }
        cluster_wait();     // acquire: full w resident in sAct

        // ---- xe part-B (w region), then store partials ----
        mmT<4, 40>(sW2T + j0B * 40 + row0x, sAct + b0x * S_ACT + j0B, x01, x23);
        {
            float* P = sPar + cx * PARX + b0x * PS_X + row0x;
#pragma unroll
            for (int kk = 0; kk < 4; kk++)
                *reinterpret_cast<ulonglong2*>(P + kk * (4 * PS_X)) =
                    make_ulonglong2(x01[kk], x23[kk]);
        }
        __syncthreads();
        float xres = 0.f;
#pragma unroll
        for (int c = 0; c < 16; c++) xres += sPar[c * PARX + xb * PS_X + xr];
        if (xr < 32) {
            // direct-store x' into all 8 ranks' sAct (safe: every CTA's
            // x-readers [part-A, w-mm] precede its w-arrive, which precedes
            // our w-wait, which precedes this store)
#pragma unroll
            for (int p = 0; p < RANKS; p++) st_cluster(peer[p] + offx, xres);
        }
        cluster_arrive();   // release x stores

        // window: e outputs + d commit
        if (xr >= 32)
            out[(size_t)(g * BT + xb) * (NSTEPS * 64) + (size_t)k * 64 + re + (xr - 32)] = xres;
        sAct[d0b * S_ACT + 256 + d0j] = dpre0;
        if (i1 < 1024) sAct[d1b * S_ACT + 256 + d1j] = dpre1;

        cluster_wait();     // acquire: full x_{k+1} resident
        __syncthreads();    // d commit visible CTA-wide
    }

    // final states: x_final (act x-part), w_{N-1} (act w-part)
    if (t < 512) {
        int b = t >> 5, row = t & 31;
        size_t gb = (size_t)(g * BT + b);
        out[BASE_X + gb * 256 + rw + row] = sAct[b * S_ACT + rw + row];
        out[BASE_W + gb * 256 + rw + row] = sAct[b * S_ACT + 320 + rw + row];
    }
}

extern "C" void kernel_launch(void* const* d_in, const int* in_sizes, int n_in,
                              void* d_out, int out_size) {
    (void)in_sizes; (void)n_in; (void)out_size;
    const float* dseq = (const float*)d_in[0];
    const float* x0   = (const float*)d_in[1];
    const float* A    = (const float*)d_in[2];
    const float* B    = (const float*)d_in[3];
    const float* B2   = (const float*)d_in[4];
    const float* C    = (const float*)d_in[5];
    const float* D    = (const float*)d_in[6];
    const float* D12  = (const float*)d_in[7];
    const float* C2   = (const float*)d_in[8];
    const float* D21  = (const float*)d_in[9];
    float* out = (float*)d_out;

    fuse_kernel<<<64, 256>>>(A, B, B2, C, D, D12);

    const size_t smem_bytes = (size_t)SMEM_FLOATS * sizeof(float);
    cudaFuncSetAttribute(lure_kernel, cudaFuncAttributeMaxDynamicSharedMemorySize,
                         (int)smem_bytes);
    lure_kernel<<<GROUPS * RANKS, THREADS, smem_bytes>>>(dseq, x0, A, B, B2,
                                                         C2, D21, out);
}